// round 13
// baseline (speedup 1.0000x reference)
#include <cuda_runtime.h>
#include <cuda_fp16.h>
#include <cstdint>
#include <math.h>

constexpr int NB = 32;
constexpr int NC = 1024;
constexpr int NS = 1024;
constexpr size_t MAT = (size_t)NC * NS;           // 1M elems
constexpr size_t MB1 = 1u << 20;

// ---------------------------------------------------------------------------
// One big scratch buffer (device global — allocation-guard safe)
// ---------------------------------------------------------------------------
__device__ __align__(128) unsigned char g_buf[600 * MB1];

#define OFF_XS    (0 * 64 * MB1)
#define OFF_XI    (1 * 64 * MB1)
#define OFF_Q     (2 * 64 * MB1)
#define OFF_K     (3 * 64 * MB1)
#define OFF_VT    (4 * 64 * MB1)
#define OFF_WA    (5 * 64 * MB1)
#define OFF_NVT   (6 * 64 * MB1)
#define OFF_SF32  (7 * 64 * MB1)                  // 128MB fp32 scores
#define OFF_W0    (9 * 64 * MB1)                  // 4 x 2MB fp16 weights

// ---------------------------------------------------------------------------
// sm_80+-portable PTX helpers (NO tcgen05 — unavailable via compute_103 PTX)
// ---------------------------------------------------------------------------
__device__ __forceinline__ uint32_t smem_to_u32(const void* p) {
    uint32_t a;
    asm("{ .reg .u64 t; cvta.to.shared.u64 t, %1; cvt.u32.u64 %0, t; }" : "=r"(a) : "l"(p));
    return a;
}
__device__ __forceinline__ void cp16(uint32_t dst, const void* src) {
    asm volatile("cp.async.cg.shared.global [%0], [%1], 16;" :: "r"(dst), "l"(src) : "memory");
}
__device__ __forceinline__ void ldsm4(uint32_t* r, uint32_t addr) {
    asm volatile("ldmatrix.sync.aligned.m8n8.x4.shared.b16 {%0,%1,%2,%3}, [%4];"
        : "=r"(r[0]), "=r"(r[1]), "=r"(r[2]), "=r"(r[3]) : "r"(addr));
}
__device__ __forceinline__ void mma_f16(float* c, const uint32_t* a, const uint32_t* b) {
    asm volatile(
        "mma.sync.aligned.m16n8k16.row.col.f32.f16.f16.f32 "
        "{%0,%1,%2,%3}, {%4,%5,%6,%7}, {%8,%9}, {%0,%1,%2,%3};"
        : "+f"(c[0]), "+f"(c[1]), "+f"(c[2]), "+f"(c[3])
        : "r"(a[0]), "r"(a[1]), "r"(a[2]), "r"(a[3]), "r"(b[0]), "r"(b[1]));
}

enum { EPI_TANH = 0,      // row bias + tanh, fp16 out
       EPI_TANH_CB = 1,   // column bias + tanh, fp16 out
       EPI_SCALE = 2,     // * alpha, fp32 out
       EPI_CAST = 3,      // plain fp16 out
       EPI_BIASRES = 4 }; // row bias + residual, fp32 out

// GEMM tiling: CTA 128x256, 512 threads = 16 warps (4x4), warp tile 32x64,
// BK=128, 2-stage cp.async pipeline -> only 8 barrier/wait pairs per CTA.
constexpr int NTHREADS = 512;
constexpr int BK = 128;
constexpr int CHUNKS = NC / BK;                    // 8
constexpr int TPAD = 136;                          // padded row (fp16), 272B = 17*16B
constexpr int ATB = 128 * TPAD * 2;                // 34816 (A tile)
constexpr int BTB = 256 * TPAD * 2;                // 69632 (B tile)
constexpr int STAGE_BYTES = ATB + BTB;             // 104448
constexpr int SMEM_BYTES = 2 * STAGE_BYTES;        // 208896

// ---------------------------------------------------------------------------
// fp16 mma.sync GEMM:  D[m,n] = sum_k A[m,k]*B[n,k]  (both K-major fp16)
// All epilogues store coalesced row-major output.
// ---------------------------------------------------------------------------
template<int EPI, bool ABATCH, bool BBATCH>
__global__ __launch_bounds__(NTHREADS, 1) void gemm_mma(
    const __half* __restrict__ A, const __half* __restrict__ B,
    const float* __restrict__ bias, const float* __restrict__ resid,
    float* __restrict__ Of, __half* __restrict__ Oh,
    float alpha)
{
    extern __shared__ char smem[];
    const uint32_t sb = smem_to_u32(smem);
    const int tid = threadIdx.x, lane = tid & 31, wid = tid >> 5;
    const int warp_m = wid & 3, warp_n = wid >> 2;        // 4 x 4 warps
    const int bx = blockIdx.x, by = blockIdx.y, bz = blockIdx.z;
    const size_t bat = (size_t)bz * MAT;
    const int m0 = by * 128, n0 = bx * 256;

    const __half* srcA = A + (ABATCH ? bat : 0);
    const __half* srcB = B + (BBATCH ? bat : 0);

    auto load_chunk = [&](int chunk, int stage) {
        const int k0 = chunk * BK;
        const uint32_t sbase = sb + stage * STAGE_BYTES;
        // A: 128 rows x 128 k = 2048 cp16 (4 per thread)
        #pragma unroll
        for (int t = 0; t < 4; ++t) {
            int gi = tid + t * NTHREADS;            // 0..2047
            int r = gi >> 4, c8 = (gi & 15) * 8;
            cp16(sbase + (uint32_t)(r * TPAD + c8) * 2,
                 srcA + (size_t)(m0 + r) * 1024 + k0 + c8);
        }
        // B: 256 rows x 128 k = 4096 cp16 (8 per thread)
        #pragma unroll
        for (int t = 0; t < 8; ++t) {
            int gi = tid + t * NTHREADS;            // 0..4095
            int r = gi >> 4, c8 = (gi & 15) * 8;
            cp16(sbase + ATB + (uint32_t)(r * TPAD + c8) * 2,
                 srcB + (size_t)(n0 + r) * 1024 + k0 + c8);
        }
    };

    // prologue: stage 0
    load_chunk(0, 0);
    asm volatile("cp.async.commit_group;" ::: "memory");

    float acc[2][8][4];
    #pragma unroll
    for (int mi = 0; mi < 2; ++mi)
        #pragma unroll
        for (int ni = 0; ni < 8; ++ni)
            #pragma unroll
            for (int e = 0; e < 4; ++e) acc[mi][ni][e] = 0.f;

    for (int c = 0; c < CHUNKS; ++c) {
        // at loop top only chunk c is outstanding -> wait all, then make visible
        asm volatile("cp.async.wait_group 0;" ::: "memory");
        __syncthreads();
        // prefetch chunk c+1 into the other stage (held chunk c-1, fully
        // consumed by all warps before the barrier above) — overlaps compute(c)
        if (c + 1 < CHUNKS) {
            load_chunk(c + 1, (c + 1) & 1);
            asm volatile("cp.async.commit_group;" ::: "memory");
        }

        const uint32_t sbase = sb + (c & 1) * STAGE_BYTES;
        const uint32_t aB = sbase, bB = sbase + ATB;

        #pragma unroll
        for (int s16 = 0; s16 < 8; ++s16) {
            const int koff = s16 * 16;
            uint32_t ah[2][4];
            #pragma unroll
            for (int mi = 0; mi < 2; ++mi) {
                uint32_t ro = (uint32_t)((warp_m * 32 + mi * 16 + (lane & 15)) * TPAD) * 2
                            + (uint32_t)(koff + ((lane >> 4) << 3)) * 2;
                ldsm4(ah[mi], aB + ro);
            }
            #pragma unroll
            for (int nj = 0; nj < 4; ++nj) {
                uint32_t bh[4];
                uint32_t ro = (uint32_t)((warp_n * 64 + nj * 16 + (lane & 7) + ((lane >> 4) << 3)) * TPAD) * 2
                            + (uint32_t)(koff + (((lane >> 3) & 1) << 3)) * 2;
                ldsm4(bh, bB + ro);
                #pragma unroll
                for (int mi = 0; mi < 2; ++mi)
                    #pragma unroll
                    for (int half = 0; half < 2; ++half)
                        mma_f16(acc[mi][nj * 2 + half], ah[mi], &bh[half * 2]);
            }
        }
    }

    // ------------------------------ epilogue (all coalesced) ----------------
    const int erow = m0 + warp_m * 32;
    const int ecol = n0 + warp_n * 64;
    const int rl = lane >> 2, cl = (lane & 3) * 2;

    #pragma unroll
    for (int mi = 0; mi < 2; ++mi) {
        const int r0e = erow + mi * 16 + rl;           // rows r0e, r0e+8
        float b0 = 0.f, b1 = 0.f;
        if (EPI == EPI_TANH || EPI == EPI_BIASRES) {
            b0 = bias[r0e]; b1 = bias[r0e + 8];
        }
        #pragma unroll
        for (int ni = 0; ni < 8; ++ni) {
            const int c0e = ecol + ni * 8 + cl;
            float* a = acc[mi][ni];
            const size_t row0 = bat + (size_t)r0e * 1024 + c0e;
            const size_t row1 = bat + (size_t)(r0e + 8) * 1024 + c0e;

            if (EPI == EPI_TANH) {
                *(__half2*)(Oh + row0) = __floats2half2_rn(tanhf(a[0] + b0), tanhf(a[1] + b0));
                *(__half2*)(Oh + row1) = __floats2half2_rn(tanhf(a[2] + b1), tanhf(a[3] + b1));
            } else if (EPI == EPI_TANH_CB) {
                const float bc0 = bias[c0e], bc1 = bias[c0e + 1];
                *(__half2*)(Oh + row0) = __floats2half2_rn(tanhf(a[0] + bc0), tanhf(a[1] + bc1));
                *(__half2*)(Oh + row1) = __floats2half2_rn(tanhf(a[2] + bc0), tanhf(a[3] + bc1));
            } else if (EPI == EPI_CAST) {
                *(__half2*)(Oh + row0) = __floats2half2_rn(a[0], a[1]);
                *(__half2*)(Oh + row1) = __floats2half2_rn(a[2], a[3]);
            } else if (EPI == EPI_SCALE) {
                float2 o0{a[0] * alpha, a[1] * alpha};
                float2 o1{a[2] * alpha, a[3] * alpha};
                *(float2*)(Of + row0) = o0;
                *(float2*)(Of + row1) = o1;
            } else {  // EPI_BIASRES
                float2 r0v = *(const float2*)(resid + row0);
                float2 r1v = *(const float2*)(resid + row1);
                float2 o0{a[0] + b0 + r0v.x, a[1] + b0 + r0v.y};
                float2 o1{a[2] + b1 + r1v.x, a[3] + b1 + r1v.y};
                *(float2*)(Of + row0) = o0;
                *(float2*)(Of + row1) = o1;
            }
        }
    }
}

// ---------------------------------------------------------------------------
// fp32 -> fp16 elementwise (weights)
// ---------------------------------------------------------------------------
__global__ __launch_bounds__(256) void cast_k(const float* __restrict__ in,
                                              __half* __restrict__ o) {
    size_t i = ((size_t)blockIdx.x * 256 + threadIdx.x) * 4;
    float4 v = *(const float4*)(in + i);
    *(__half2*)(o + i)     = __floats2half2_rn(v.x, v.y);
    *(__half2*)(o + i + 2) = __floats2half2_rn(v.z, v.w);
}

// ---------------------------------------------------------------------------
// fp32 [B][C,S] -> transposed fp16 [B][S,C]
// ---------------------------------------------------------------------------
__global__ __launch_bounds__(256) void transpose_cast_k(
    const float* __restrict__ in, __half* __restrict__ o) {
    __shared__ float t[32][33];
    const int tx = threadIdx.x, ty = threadIdx.y;   // 32x8
    const int s0 = blockIdx.x * 32, c0 = blockIdx.y * 32;
    const size_t bat = (size_t)blockIdx.z * MAT;
    #pragma unroll
    for (int i = 0; i < 4; ++i)
        t[ty + 8 * i][tx] = in[bat + (size_t)(c0 + ty + 8 * i) * 1024 + s0 + tx];
    __syncthreads();
    #pragma unroll
    for (int i = 0; i < 4; ++i)
        o[bat + (size_t)(s0 + ty + 8 * i) * 1024 + c0 + tx] = __float2half(t[tx][ty + 8 * i]);
}

// ---------------------------------------------------------------------------
// Row softmax fp32 -> fp16 weights
// ---------------------------------------------------------------------------
__global__ __launch_bounds__(256) void softmax_cast_k(
    const float* __restrict__ data, __half* __restrict__ o) {
    __shared__ float red[8];
    __shared__ float bval;
    const size_t row = blockIdx.x;
    const float* p = data + row * (size_t)NC;
    const int tid = threadIdx.x, lane = tid & 31, wid = tid >> 5;

    float4 v = ((const float4*)p)[tid];
    float mx = fmaxf(fmaxf(v.x, v.y), fmaxf(v.z, v.w));
    #pragma unroll
    for (int off = 16; off > 0; off >>= 1) mx = fmaxf(mx, __shfl_xor_sync(0xffffffffu, mx, off));
    if (lane == 0) red[wid] = mx;
    __syncthreads();
    if (tid < 32) {
        float t = (tid < 8) ? red[tid] : -INFINITY;
        #pragma unroll
        for (int off = 4; off > 0; off >>= 1) t = fmaxf(t, __shfl_xor_sync(0xffffffffu, t, off));
        if (tid == 0) bval = t;
    }
    __syncthreads();
    mx = bval;
    v.x = expf(v.x - mx); v.y = expf(v.y - mx);
    v.z = expf(v.z - mx); v.w = expf(v.w - mx);
    float s = (v.x + v.y) + (v.z + v.w);
    #pragma unroll
    for (int off = 16; off > 0; off >>= 1) s += __shfl_xor_sync(0xffffffffu, s, off);
    __syncthreads();
    if (lane == 0) red[wid] = s;
    __syncthreads();
    if (tid < 32) {
        float t = (tid < 8) ? red[tid] : 0.f;
        #pragma unroll
        for (int off = 4; off > 0; off >>= 1) t += __shfl_xor_sync(0xffffffffu, t, off);
        if (tid == 0) bval = t;
    }
    __syncthreads();
    const float inv = 1.f / bval;
    const size_t base = row * (size_t)NC + 4 * tid;
    *(__half2*)(o + base)     = __floats2half2_rn(v.x * inv, v.y * inv);
    *(__half2*)(o + base + 2) = __floats2half2_rn(v.z * inv, v.w * inv);
}

// ---------------------------------------------------------------------------
extern "C" void kernel_launch(void* const* d_in, const int* in_sizes, int n_in,
                              void* d_out, int out_size)
{
    const float* shape_map = (const float*)d_in[0];
    const float* img_map   = (const float*)d_in[1];
    const float* wq = (const float*)d_in[2];
    const float* bq = (const float*)d_in[3];
    const float* wk = (const float*)d_in[4];
    const float* bk = (const float*)d_in[5];
    const float* wv = (const float*)d_in[6];
    const float* bv = (const float*)d_in[7];
    const float* wc = (const float*)d_in[8];
    const float* bc = (const float*)d_in[9];
    float* out = (float*)d_out;

    unsigned char* buf;
    cudaGetSymbolAddress((void**)&buf, g_buf);
    __half* XS  = (__half*)(buf + OFF_XS);
    __half* XI  = (__half*)(buf + OFF_XI);
    __half* Q   = (__half*)(buf + OFF_Q);
    __half* K   = (__half*)(buf + OFF_K);
    __half* VT  = (__half*)(buf + OFF_VT);
    __half* WA  = (__half*)(buf + OFF_WA);
    __half* NVT = (__half*)(buf + OFF_NVT);
    float*  SF  = (float*)(buf + OFF_SF32);
    __half* W[4];   // q,k,v,c
    for (int i = 0; i < 4; ++i) W[i] = (__half*)(buf + OFF_W0 + (size_t)i * 2 * MB1);

    cudaFuncSetAttribute(gemm_mma<EPI_TANH, false, true>,    cudaFuncAttributeMaxDynamicSharedMemorySize, SMEM_BYTES);
    cudaFuncSetAttribute(gemm_mma<EPI_TANH_CB, true, false>, cudaFuncAttributeMaxDynamicSharedMemorySize, SMEM_BYTES);
    cudaFuncSetAttribute(gemm_mma<EPI_SCALE, true, true>,    cudaFuncAttributeMaxDynamicSharedMemorySize, SMEM_BYTES);
    cudaFuncSetAttribute(gemm_mma<EPI_CAST, true, true>,     cudaFuncAttributeMaxDynamicSharedMemorySize, SMEM_BYTES);
    cudaFuncSetAttribute(gemm_mma<EPI_BIASRES, false, true>, cudaFuncAttributeMaxDynamicSharedMemorySize, SMEM_BYTES);

    const dim3 grid(4, 8, NB);   // n-tiles(256) x m-tiles(128) x batch

    // converts
    cast_k<<<MAT / 1024, 256>>>(wq, W[0]);
    cast_k<<<MAT / 1024, 256>>>(wk, W[1]);
    cast_k<<<MAT / 1024, 256>>>(wv, W[2]);
    cast_k<<<MAT / 1024, 256>>>(wc, W[3]);
    transpose_cast_k<<<dim3(32, 32, NB), dim3(32, 8)>>>(shape_map, XS);
    transpose_cast_k<<<dim3(32, 32, NB), dim3(32, 8)>>>(img_map, XI);

    // Q[c,s] = tanh(Wq@Xs + bq):  A=Wq [C,C], B=XS [S,C] batched -> [C,S]
    gemm_mma<EPI_TANH, false, true><<<grid, NTHREADS, SMEM_BYTES>>>(W[0], XS, bq, nullptr, nullptr, Q, 0.f);
    gemm_mma<EPI_TANH, false, true><<<grid, NTHREADS, SMEM_BYTES>>>(W[1], XI, bk, nullptr, nullptr, K, 0.f);
    // VT[s,c] = tanh(sum_d XI[s,d]*Wv[c,d] + bv[c]):  A=XI batched, B=Wv -> [S,C] coalesced
    gemm_mma<EPI_TANH_CB, true, false><<<grid, NTHREADS, SMEM_BYTES>>>(XI, W[2], bv, nullptr, nullptr, VT, 0.f);
    // scores[c,d] = (Q @ K^T)/32 -> fp32 [C,C]
    gemm_mma<EPI_SCALE, true, true><<<grid, NTHREADS, SMEM_BYTES>>>(Q, K, nullptr, nullptr, SF, nullptr, 0.03125f);
    // softmax rows -> fp16 weights
    softmax_cast_k<<<NB * NC, 256>>>(SF, WA);
    // NVT[s,c] = sum_d VT[s,d]*WA[c,d] = new_v^T -> [S,C] coalesced
    gemm_mma<EPI_CAST, true, true><<<grid, NTHREADS, SMEM_BYTES>>>(VT, WA, nullptr, nullptr, nullptr, NVT, 0.f);
    // out[c,s] = sum_d Wc[c,d]*NVT[s,d] + bc[c] + shape_map  -> fp32 [C,S]
    gemm_mma<EPI_BIASRES, false, true><<<grid, NTHREADS, SMEM_BYTES>>>(W[3], NVT, bc, shape_map, out, nullptr, 0.f);
}

// round 14
// speedup vs baseline: 1.0369x; 1.0369x over previous
#include <cuda_runtime.h>
#include <cuda_fp16.h>
#include <cstdint>
#include <math.h>

constexpr int NB = 32;
constexpr int NC = 1024;
constexpr int NS = 1024;
constexpr size_t MAT = (size_t)NC * NS;           // 1M elems
constexpr size_t MB1 = 1u << 20;

// ---------------------------------------------------------------------------
// One big scratch buffer (device global — allocation-guard safe)
// ---------------------------------------------------------------------------
__device__ __align__(128) unsigned char g_buf[600 * MB1];

#define OFF_XS    (0 * 64 * MB1)
#define OFF_XI    (1 * 64 * MB1)
#define OFF_Q     (2 * 64 * MB1)
#define OFF_K     (3 * 64 * MB1)
#define OFF_VT    (4 * 64 * MB1)
#define OFF_WA    (5 * 64 * MB1)
#define OFF_NVT   (6 * 64 * MB1)
#define OFF_SF32  (7 * 64 * MB1)                  // 128MB fp32 exp(scores)
#define OFF_W0    (9 * 64 * MB1)                  // 4 x 2MB fp16 weights

// ---------------------------------------------------------------------------
// sm_80+-portable PTX helpers (NO tcgen05 — unavailable via compute_103 PTX)
// ---------------------------------------------------------------------------
__device__ __forceinline__ uint32_t smem_to_u32(const void* p) {
    uint32_t a;
    asm("{ .reg .u64 t; cvta.to.shared.u64 t, %1; cvt.u32.u64 %0, t; }" : "=r"(a) : "l"(p));
    return a;
}
__device__ __forceinline__ void cp16(uint32_t dst, const void* src) {
    asm volatile("cp.async.cg.shared.global [%0], [%1], 16;" :: "r"(dst), "l"(src) : "memory");
}
__device__ __forceinline__ void ldsm4(uint32_t* r, uint32_t addr) {
    asm volatile("ldmatrix.sync.aligned.m8n8.x4.shared.b16 {%0,%1,%2,%3}, [%4];"
        : "=r"(r[0]), "=r"(r[1]), "=r"(r[2]), "=r"(r[3]) : "r"(addr));
}
__device__ __forceinline__ void mma_f16(float* c, const uint32_t* a, const uint32_t* b) {
    asm volatile(
        "mma.sync.aligned.m16n8k16.row.col.f32.f16.f16.f32 "
        "{%0,%1,%2,%3}, {%4,%5,%6,%7}, {%8,%9}, {%0,%1,%2,%3};"
        : "+f"(c[0]), "+f"(c[1]), "+f"(c[2]), "+f"(c[3])
        : "r"(a[0]), "r"(a[1]), "r"(a[2]), "r"(a[3]), "r"(b[0]), "r"(b[1]));
}

enum { EPI_TANH = 0,      // row bias + tanh, fp16 out
       EPI_TANH_CB = 1,   // column bias + tanh, fp16 out
       EPI_EXP = 2,       // exp(x*alpha), fp32 out (softmax numerator; scores bounded)
       EPI_CAST = 3,      // plain fp16 out
       EPI_BIASRES = 4 }; // row bias + residual, fp32 out

// GEMM tiling: CTA 128x256, 512 threads = 16 warps (4x4), warp tile 32x64,
// BK=64, 4-stage cp.async pipeline (wait_group 2 -> wait almost never blocks).
constexpr int NTHREADS = 512;
constexpr int STAGES = 4;
constexpr int BK = 64;
constexpr int CHUNKS = NC / BK;                    // 16
constexpr int TPAD = 72;                           // padded row (fp16), 144B
constexpr int ATB = 128 * TPAD * 2;                // 18432 (A tile)
constexpr int BTB = 256 * TPAD * 2;                // 36864 (B tile)
constexpr int STAGE_BYTES = ATB + BTB;             // 55296
constexpr int SMEM_BYTES = STAGES * STAGE_BYTES;   // 221184

// ---------------------------------------------------------------------------
// fp16 mma.sync GEMM:  D[m,n] = sum_k A[m,k]*B[n,k]  (both K-major fp16)
// All epilogues store coalesced row-major output.
// ---------------------------------------------------------------------------
template<int EPI, bool ABATCH, bool BBATCH>
__global__ __launch_bounds__(NTHREADS, 1) void gemm_mma(
    const __half* __restrict__ A, const __half* __restrict__ B,
    const float* __restrict__ bias, const float* __restrict__ resid,
    float* __restrict__ Of, __half* __restrict__ Oh,
    float alpha)
{
    extern __shared__ char smem[];
    const uint32_t sb = smem_to_u32(smem);
    const int tid = threadIdx.x, lane = tid & 31, wid = tid >> 5;
    const int warp_m = wid & 3, warp_n = wid >> 2;        // 4 x 4 warps
    const int bx = blockIdx.x, by = blockIdx.y, bz = blockIdx.z;
    const size_t bat = (size_t)bz * MAT;
    const int m0 = by * 128, n0 = bx * 256;

    const __half* srcA = A + (ABATCH ? bat : 0);
    const __half* srcB = B + (BBATCH ? bat : 0);

    auto load_chunk = [&](int chunk, int stage) {
        const int k0 = chunk * BK;
        const uint32_t sbase = sb + stage * STAGE_BYTES;
        // A: 128 rows x 64 k = 1024 cp16 (2 per thread)
        #pragma unroll
        for (int t = 0; t < 2; ++t) {
            int gi = tid + t * NTHREADS;            // 0..1023
            int r = gi >> 3, c8 = (gi & 7) * 8;
            cp16(sbase + (uint32_t)(r * TPAD + c8) * 2,
                 srcA + (size_t)(m0 + r) * 1024 + k0 + c8);
        }
        // B: 256 rows x 64 k = 2048 cp16 (4 per thread)
        #pragma unroll
        for (int t = 0; t < 4; ++t) {
            int gi = tid + t * NTHREADS;            // 0..2047
            int r = gi >> 3, c8 = (gi & 7) * 8;
            cp16(sbase + ATB + (uint32_t)(r * TPAD + c8) * 2,
                 srcB + (size_t)(n0 + r) * 1024 + k0 + c8);
        }
    };

    // prologue: stages 0,1,2
    load_chunk(0, 0);
    asm volatile("cp.async.commit_group;" ::: "memory");
    load_chunk(1, 1);
    asm volatile("cp.async.commit_group;" ::: "memory");
    load_chunk(2, 2);
    asm volatile("cp.async.commit_group;" ::: "memory");

    float acc[2][8][4];
    #pragma unroll
    for (int mi = 0; mi < 2; ++mi)
        #pragma unroll
        for (int ni = 0; ni < 8; ++ni)
            #pragma unroll
            for (int e = 0; e < 4; ++e) acc[mi][ni][e] = 0.f;

    for (int c = 0; c < CHUNKS; ++c) {
        asm volatile("cp.async.wait_group 2;" ::: "memory");   // chunk c arrived
        __syncthreads();

        const int nc = c + STAGES - 1;
        if (nc < CHUNKS) load_chunk(nc, nc % STAGES);
        asm volatile("cp.async.commit_group;" ::: "memory");   // unconditional: keep count

        const uint32_t sbase = sb + (c % STAGES) * STAGE_BYTES;
        const uint32_t aB = sbase, bB = sbase + ATB;

        #pragma unroll
        for (int s16 = 0; s16 < 4; ++s16) {
            const int koff = s16 * 16;
            uint32_t ah[2][4];
            #pragma unroll
            for (int mi = 0; mi < 2; ++mi) {
                uint32_t ro = (uint32_t)((warp_m * 32 + mi * 16 + (lane & 15)) * TPAD) * 2
                            + (uint32_t)(koff + ((lane >> 4) << 3)) * 2;
                ldsm4(ah[mi], aB + ro);
            }
            #pragma unroll
            for (int nj = 0; nj < 4; ++nj) {
                uint32_t bh[4];
                uint32_t ro = (uint32_t)((warp_n * 64 + nj * 16 + (lane & 7) + ((lane >> 4) << 3)) * TPAD) * 2
                            + (uint32_t)(koff + (((lane >> 3) & 1) << 3)) * 2;
                ldsm4(bh, bB + ro);
                #pragma unroll
                for (int mi = 0; mi < 2; ++mi)
                    #pragma unroll
                    for (int half = 0; half < 2; ++half)
                        mma_f16(acc[mi][nj * 2 + half], ah[mi], &bh[half * 2]);
            }
        }
    }

    // ------------------------------ epilogue (all coalesced) ----------------
    const int erow = m0 + warp_m * 32;
    const int ecol = n0 + warp_n * 64;
    const int rl = lane >> 2, cl = (lane & 3) * 2;

    #pragma unroll
    for (int mi = 0; mi < 2; ++mi) {
        const int r0e = erow + mi * 16 + rl;           // rows r0e, r0e+8
        float b0 = 0.f, b1 = 0.f;
        if (EPI == EPI_TANH || EPI == EPI_BIASRES) {
            b0 = bias[r0e]; b1 = bias[r0e + 8];
        }
        #pragma unroll
        for (int ni = 0; ni < 8; ++ni) {
            const int c0e = ecol + ni * 8 + cl;
            float* a = acc[mi][ni];
            const size_t row0 = bat + (size_t)r0e * 1024 + c0e;
            const size_t row1 = bat + (size_t)(r0e + 8) * 1024 + c0e;

            if (EPI == EPI_TANH) {
                *(__half2*)(Oh + row0) = __floats2half2_rn(tanhf(a[0] + b0), tanhf(a[1] + b0));
                *(__half2*)(Oh + row1) = __floats2half2_rn(tanhf(a[2] + b1), tanhf(a[3] + b1));
            } else if (EPI == EPI_TANH_CB) {
                const float bc0 = bias[c0e], bc1 = bias[c0e + 1];
                *(__half2*)(Oh + row0) = __floats2half2_rn(tanhf(a[0] + bc0), tanhf(a[1] + bc1));
                *(__half2*)(Oh + row1) = __floats2half2_rn(tanhf(a[2] + bc0), tanhf(a[3] + bc1));
            } else if (EPI == EPI_CAST) {
                *(__half2*)(Oh + row0) = __floats2half2_rn(a[0], a[1]);
                *(__half2*)(Oh + row1) = __floats2half2_rn(a[2], a[3]);
            } else if (EPI == EPI_EXP) {
                // scores bounded (|score*alpha| <= 32): exp without max-subtract
                float2 o0{expf(a[0] * alpha), expf(a[1] * alpha)};
                float2 o1{expf(a[2] * alpha), expf(a[3] * alpha)};
                *(float2*)(Of + row0) = o0;
                *(float2*)(Of + row1) = o1;
            } else {  // EPI_BIASRES
                float2 r0v = *(const float2*)(resid + row0);
                float2 r1v = *(const float2*)(resid + row1);
                float2 o0{a[0] + b0 + r0v.x, a[1] + b0 + r0v.y};
                float2 o1{a[2] + b1 + r1v.x, a[3] + b1 + r1v.y};
                *(float2*)(Of + row0) = o0;
                *(float2*)(Of + row1) = o1;
            }
        }
    }
}

// ---------------------------------------------------------------------------
// fp32 -> fp16 elementwise, 4 tensors in one launch (grid.y selects)
// ---------------------------------------------------------------------------
__global__ __launch_bounds__(256) void cast4_k(
    const float* __restrict__ i0, const float* __restrict__ i1,
    const float* __restrict__ i2, const float* __restrict__ i3,
    __half* __restrict__ o0, __half* __restrict__ o1,
    __half* __restrict__ o2, __half* __restrict__ o3)
{
    const float* in; __half* o;
    switch (blockIdx.y) {
        case 0: in = i0; o = o0; break;
        case 1: in = i1; o = o1; break;
        case 2: in = i2; o = o2; break;
        default: in = i3; o = o3; break;
    }
    size_t i = ((size_t)blockIdx.x * 256 + threadIdx.x) * 4;
    float4 v = *(const float4*)(in + i);
    *(__half2*)(o + i)     = __floats2half2_rn(v.x, v.y);
    *(__half2*)(o + i + 2) = __floats2half2_rn(v.z, v.w);
}

// ---------------------------------------------------------------------------
// fp32 [B][C,S] -> transposed fp16 [B][S,C], 2 tensors in one launch
// ---------------------------------------------------------------------------
__global__ __launch_bounds__(256) void transpose_cast2_k(
    const float* __restrict__ in0, __half* __restrict__ o0,
    const float* __restrict__ in1, __half* __restrict__ o1)
{
    __shared__ float t[32][33];
    const int tx = threadIdx.x, ty = threadIdx.y;   // 32x8
    const int s0 = blockIdx.x * 32, c0 = blockIdx.y * 32;
    const int z = blockIdx.z;
    const float* in = (z < NB) ? in0 : in1;
    __half* o = (z < NB) ? o0 : o1;
    const size_t bat = (size_t)(z & (NB - 1)) * MAT;
    #pragma unroll
    for (int i = 0; i < 4; ++i)
        t[ty + 8 * i][tx] = in[bat + (size_t)(c0 + ty + 8 * i) * 1024 + s0 + tx];
    __syncthreads();
    #pragma unroll
    for (int i = 0; i < 4; ++i)
        o[bat + (size_t)(s0 + ty + 8 * i) * 1024 + c0 + tx] = __float2half(t[tx][ty + 8 * i]);
}

// ---------------------------------------------------------------------------
// Row normalize: in = exp(scores) fp32; out = in/rowsum as fp16
// ---------------------------------------------------------------------------
__global__ __launch_bounds__(256) void sumnorm_k(
    const float* __restrict__ data, __half* __restrict__ o) {
    __shared__ float red[8];
    __shared__ float bval;
    const size_t row = blockIdx.x;
    const float* p = data + row * (size_t)NC;
    const int tid = threadIdx.x, lane = tid & 31, wid = tid >> 5;

    float4 v = ((const float4*)p)[tid];
    float s = (v.x + v.y) + (v.z + v.w);
    #pragma unroll
    for (int off = 16; off > 0; off >>= 1) s += __shfl_xor_sync(0xffffffffu, s, off);
    if (lane == 0) red[wid] = s;
    __syncthreads();
    if (tid < 32) {
        float t = (tid < 8) ? red[tid] : 0.f;
        #pragma unroll
        for (int off = 4; off > 0; off >>= 1) t += __shfl_xor_sync(0xffffffffu, t, off);
        if (tid == 0) bval = t;
    }
    __syncthreads();
    const float inv = 1.f / bval;
    const size_t base = row * (size_t)NC + 4 * tid;
    *(__half2*)(o + base)     = __floats2half2_rn(v.x * inv, v.y * inv);
    *(__half2*)(o + base + 2) = __floats2half2_rn(v.z * inv, v.w * inv);
}

// ---------------------------------------------------------------------------
extern "C" void kernel_launch(void* const* d_in, const int* in_sizes, int n_in,
                              void* d_out, int out_size)
{
    const float* shape_map = (const float*)d_in[0];
    const float* img_map   = (const float*)d_in[1];
    const float* wq = (const float*)d_in[2];
    const float* bq = (const float*)d_in[3];
    const float* wk = (const float*)d_in[4];
    const float* bk = (const float*)d_in[5];
    const float* wv = (const float*)d_in[6];
    const float* bv = (const float*)d_in[7];
    const float* wc = (const float*)d_in[8];
    const float* bc = (const float*)d_in[9];
    float* out = (float*)d_out;

    unsigned char* buf;
    cudaGetSymbolAddress((void**)&buf, g_buf);
    __half* XS  = (__half*)(buf + OFF_XS);
    __half* XI  = (__half*)(buf + OFF_XI);
    __half* Q   = (__half*)(buf + OFF_Q);
    __half* K   = (__half*)(buf + OFF_K);
    __half* VT  = (__half*)(buf + OFF_VT);
    __half* WA  = (__half*)(buf + OFF_WA);
    __half* NVT = (__half*)(buf + OFF_NVT);
    float*  SF  = (float*)(buf + OFF_SF32);
    __half* W[4];   // q,k,v,c
    for (int i = 0; i < 4; ++i) W[i] = (__half*)(buf + OFF_W0 + (size_t)i * 2 * MB1);

    cudaFuncSetAttribute(gemm_mma<EPI_TANH, false, true>,    cudaFuncAttributeMaxDynamicSharedMemorySize, SMEM_BYTES);
    cudaFuncSetAttribute(gemm_mma<EPI_TANH_CB, true, false>, cudaFuncAttributeMaxDynamicSharedMemorySize, SMEM_BYTES);
    cudaFuncSetAttribute(gemm_mma<EPI_EXP, true, true>,      cudaFuncAttributeMaxDynamicSharedMemorySize, SMEM_BYTES);
    cudaFuncSetAttribute(gemm_mma<EPI_CAST, true, true>,     cudaFuncAttributeMaxDynamicSharedMemorySize, SMEM_BYTES);
    cudaFuncSetAttribute(gemm_mma<EPI_BIASRES, false, true>, cudaFuncAttributeMaxDynamicSharedMemorySize, SMEM_BYTES);

    const dim3 grid(4, 8, NB);   // n-tiles(256) x m-tiles(128) x batch

    // converts (2 launches)
    cast4_k<<<dim3(MAT / 1024, 4), 256>>>(wq, wk, wv, wc, W[0], W[1], W[2], W[3]);
    transpose_cast2_k<<<dim3(32, 32, 2 * NB), dim3(32, 8)>>>(shape_map, XS, img_map, XI);

    // Q[c,s] = tanh(Wq@Xs + bq):  A=Wq [C,C], B=XS [S,C] batched -> [C,S]
    gemm_mma<EPI_TANH, false, true><<<grid, NTHREADS, SMEM_BYTES>>>(W[0], XS, bq, nullptr, nullptr, Q, 0.f);
    gemm_mma<EPI_TANH, false, true><<<grid, NTHREADS, SMEM_BYTES>>>(W[1], XI, bk, nullptr, nullptr, K, 0.f);
    // VT[s,c] = tanh(sum_d XI[s,d]*Wv[c,d] + bv[c]):  A=XI batched, B=Wv -> [S,C] coalesced
    gemm_mma<EPI_TANH_CB, true, false><<<grid, NTHREADS, SMEM_BYTES>>>(XI, W[2], bv, nullptr, nullptr, VT, 0.f);
    // E[c,d] = exp((Q @ K^T)/32) -> fp32 [C,C]  (softmax numerator, no max needed)
    gemm_mma<EPI_EXP, true, true><<<grid, NTHREADS, SMEM_BYTES>>>(Q, K, nullptr, nullptr, SF, nullptr, 0.03125f);
    // weights = E / rowsum(E) -> fp16
    sumnorm_k<<<NB * NC, 256>>>(SF, WA);
    // NVT[s,c] = sum_d VT[s,d]*WA[c,d] = new_v^T -> [S,C] coalesced
    gemm_mma<EPI_CAST, true, true><<<grid, NTHREADS, SMEM_BYTES>>>(VT, WA, nullptr, nullptr, nullptr, NVT, 0.f);
    // out[c,s] = sum_d Wc[c,d]*NVT[s,d] + bc[c] + shape_map  -> fp32 [C,S]
    gemm_mma<EPI_BIASRES, false, true><<<grid, NTHREADS, SMEM_BYTES>>>(W[3], NVT, bc, shape_map, out, nullptr, 0.f);
}